// round 9
// baseline (speedup 1.0000x reference)
#include <cuda_runtime.h>
#include <cuda_bf16.h>

#define NN   100000
#define INC  128
#define OUTC 200
#define EE   1600000
#define KP   64            /* k-pairs (INC/2) */

typedef unsigned int u32;
typedef unsigned long long u64;

// Scratch (static __device__ — no runtime allocation allowed)
__device__ __align__(128) float g_dinv[NN];
__device__ __align__(128) float g_agg[(long long)NN * INC];
__device__ __align__(128) u32   g_apk[(long long)NN * INC];  // [row][kp][{hi,lo}] bf16x2
__device__ int g_is64;

// ---------------------------------------------------------------------------
// bf16 2-term split: a ~= hi + lo (each bf16), ~19-bit effective precision
__device__ __forceinline__ void bsplit(float a, unsigned short& h, unsigned short& l) {
    __nv_bfloat16 hb = __float2bfloat16_rn(a);
    float r = a - __bfloat162float(hb);
    __nv_bfloat16 lb = __float2bfloat16_rn(r);
    h = *(unsigned short*)&hb;
    l = *(unsigned short*)&lb;
}

__device__ __forceinline__ void mma_bf16(float* c, const u32* a, u32 b0, u32 b1) {
    asm("mma.sync.aligned.m16n8k16.row.col.f32.bf16.bf16.f32 "
        "{%0,%1,%2,%3}, {%4,%5,%6,%7}, {%8,%9}, {%0,%1,%2,%3};"
        : "+f"(c[0]), "+f"(c[1]), "+f"(c[2]), "+f"(c[3])
        : "r"(a[0]), "r"(a[1]), "r"(a[2]), "r"(a[3]), "r"(b0), "r"(b1));
}

// ---------------------------------------------------------------------------
// 1) degree init + dtype probe fused
__global__ void k_deg_init(const unsigned* __restrict__ ei_words) {
    int v = blockIdx.x * blockDim.x + threadIdx.x;
    if (v < NN) g_dinv[v] = 1.0f;
    if (v == 0) {
        int is64 = 1;
        for (int i = 0; i < 64; i++)
            if (ei_words[2 * i + 1] != 0u) { is64 = 0; break; }
        g_is64 = is64;
    }
}

__device__ __forceinline__ int load_idx(const void* ei, long long pos) {
    if (g_is64) return (int)((const long long*)ei)[pos];
    return ((const int*)ei)[pos];
}

// 2) degree count over edge destinations
__global__ void k_deg_count(const void* __restrict__ ei) {
    int e = blockIdx.x * blockDim.x + threadIdx.x;
    if (e < EE) {
        int v = load_idx(ei, (long long)EE + e);
        atomicAdd(&g_dinv[v], 1.0f);
    }
}

// 3) dinv = rsqrt(deg); init agg[v] = dinv[v]^2 * x[v]  (self-loop message)
__global__ void k_dinv_self(const float* __restrict__ x) {
    int gw   = (blockIdx.x * blockDim.x + threadIdx.x) >> 5;
    int lane = threadIdx.x & 31;
    if (gw >= NN) return;
    float di = 0.0f;
    if (lane == 0) {
        di = rsqrtf(g_dinv[gw]);
        g_dinv[gw] = di;
    }
    di = __shfl_sync(0xffffffffu, di, 0);
    float w = di * di;
    float4 t = ((const float4*)(x + (long long)gw * INC))[lane];
    float4 o;
    o.x = t.x * w; o.y = t.y * w; o.z = t.z * w; o.w = t.w * w;
    ((float4*)(g_agg + (long long)gw * INC))[lane] = o;
}

// 4) edge scatter: agg[v] += dinv[u]*dinv[v] * x[u]
__global__ void k_scatter(const void* __restrict__ ei,
                          const float* __restrict__ x) {
    int e    = (int)(((long long)blockIdx.x * blockDim.x + threadIdx.x) >> 5);
    int lane = threadIdx.x & 31;
    if (e >= EE) return;
    int u = load_idx(ei, e);                   // src
    int v = load_idx(ei, (long long)EE + e);   // dst
    float w = g_dinv[u] * g_dinv[v];
    float4 t = ((const float4*)(x + (long long)u * INC))[lane];
    float* dst = g_agg + (long long)v * INC + lane * 4;
    asm volatile("red.global.add.v4.f32 [%0], {%1, %2, %3, %4};"
                 :: "l"(dst), "f"(t.x * w), "f"(t.y * w), "f"(t.z * w), "f"(t.w * w)
                 : "memory");
}

// 4b) pre-split agg -> packed bf16 (hi,lo) pairs for the tensor GEMM
//     thread i handles k-pair kp of row r (i = r*64+kp): reads float2,
//     writes 8B (hi-pair u32, lo-pair u32). Fully coalesced.
__global__ void k_split_a() {
    long long i = (long long)blockIdx.x * blockDim.x + threadIdx.x;
    if (i >= (long long)NN * KP) return;
    float2 a = *(const float2*)(g_agg + 2 * i);
    unsigned short h0, l0, h1, l1;
    bsplit(a.x, h0, l0);
    bsplit(a.y, h1, l1);
    u32 hip = ((u32)h1 << 16) | h0;
    u32 lop = ((u32)l1 << 16) | l0;
    u64 packed = ((u64)lop << 32) | hip;
    *(u64*)(g_apk + 2 * i) = packed;
}

// ---------------------------------------------------------------------------
// 5) tensor GEMM: [mu | logstd] = agg @ [W1 | W2] + [b1 | b2]
//    mma.m16n8k16 bf16, 3-term split (ah*wh + ah*wl + al*wh), W pre-split in
//    smem [col][kpair][{hi,lo}] (one LDS.64 per B fragment), A pre-split in
//    g_apk (LDG.64 per fragment). MTILE=128: warp = 32-row block x 200-col
//    half, 2 row-sets share each B load.
#define CSTRIDE 132                          /* u32 per col (pad 4: 2-way max) */
#define GEMM_SMEM (400 * CSTRIDE * 4 + 1600) /* 212800 B */
#define MTILE   128
#define NTILES  ((NN + MTILE - 1) / MTILE)   /* 782 */

__global__ __launch_bounds__(256, 1) void k_gemm(
    const float* __restrict__ W1, const float* __restrict__ b1,
    const float* __restrict__ W2, const float* __restrict__ b2,
    float* __restrict__ out)
{
    extern __shared__ u32 sm[];
    u32*   Wpk     = sm;                       // [400][CSTRIDE]
    float* bias_sm = (float*)(sm + 400 * CSTRIDE);  // [400]
    int tid = threadIdx.x;

    // Stage split W (once per CTA): i = col*64 + kp
    for (int i = tid; i < 400 * KP; i += 256) {
        int col = i >> 6;
        int kp  = i & 63;
        int cc  = (col < 200) ? col : col - 200;
        const float* WW = (col < 200) ? W1 : W2;
        float w0 = WW[(2 * kp)     * 200 + cc];
        float w1 = WW[(2 * kp + 1) * 200 + cc];
        unsigned short h0, l0, h1, l1;
        bsplit(w0, h0, l0);
        bsplit(w1, h1, l1);
        Wpk[col * CSTRIDE + 2 * kp]     = ((u32)h1 << 16) | h0;
        Wpk[col * CSTRIDE + 2 * kp + 1] = ((u32)l1 << 16) | l0;
    }
    for (int i = tid; i < 400; i += 256)
        bias_sm[i] = (i < 200) ? b1[i] : b2[i - 200];

    int wid  = tid >> 5;
    int lane = tid & 31;
    int g    = lane >> 2;         // 0..7
    int tig  = lane & 3;          // 0..3
    int rb   = wid & 3;           // 32-row block
    int n0w  = (wid >> 2) * 200;  // col-half base

    float* mu = out;
    float* ls = out + (long long)NN * OUTC;
    __syncthreads();

    for (int tile = blockIdx.x; tile < NTILES; tile += gridDim.x) {
        int base = tile * MTILE + rb * 32;

        float acc[2][25][4];
        #pragma unroll
        for (int s = 0; s < 2; s++)
            #pragma unroll
            for (int nb = 0; nb < 25; nb++)
                #pragma unroll
                for (int i = 0; i < 4; i++) acc[s][nb][i] = 0.0f;

        #pragma unroll
        for (int ks = 0; ks < 8; ks++) {
            int kp0 = ks * 8 + tig;
            int kp1 = kp0 + 4;

            // A fragments for both row-sets: rows (base+s*16+g) and (+8)
            u32 ah[2][4], al[2][4];
            #pragma unroll
            for (int s = 0; s < 2; s++) {
                int rA = base + s * 16 + g;
                int rB = rA + 8;
                long long cA = (long long)((rA < NN) ? rA : 0) * INC;
                long long cB = (long long)((rB < NN) ? rB : 0) * INC;
                u64 p;
                p = *(const u64*)(g_apk + cA + 2 * kp0);
                ah[s][0] = (u32)p;  al[s][0] = (u32)(p >> 32);
                p = *(const u64*)(g_apk + cB + 2 * kp0);
                ah[s][1] = (u32)p;  al[s][1] = (u32)(p >> 32);
                p = *(const u64*)(g_apk + cA + 2 * kp1);
                ah[s][2] = (u32)p;  al[s][2] = (u32)(p >> 32);
                p = *(const u64*)(g_apk + cB + 2 * kp1);
                ah[s][3] = (u32)p;  al[s][3] = (u32)(p >> 32);
            }

            #pragma unroll
            for (int nb = 0; nb < 25; nb++) {
                int col = n0w + nb * 8 + g;
                uint2 b0 = *(const uint2*)(Wpk + col * CSTRIDE + 2 * kp0);
                uint2 b1 = *(const uint2*)(Wpk + col * CSTRIDE + 2 * kp1);
                #pragma unroll
                for (int s = 0; s < 2; s++) {
                    mma_bf16(acc[s][nb], ah[s], b0.x, b1.x);  // hi*hi
                    mma_bf16(acc[s][nb], ah[s], b0.y, b1.y);  // hi*lo
                    mma_bf16(acc[s][nb], al[s], b0.x, b1.x);  // lo*hi
                }
            }
        }

        // Epilogue: c0,c1 -> row rA, c2,c3 -> row rA+8; bias from smem
        #pragma unroll
        for (int s = 0; s < 2; s++) {
            int rA = base + s * 16 + g;
            int rB = rA + 8;
            #pragma unroll
            for (int nb = 0; nb < 25; nb++) {
                int c = n0w + nb * 8 + 2 * tig;
                float bx = bias_sm[c], by = bias_sm[c + 1];
                float* obase = (c < 200) ? mu : ls;
                int cc = (c < 200) ? c : c - 200;
                if (rA < NN) {
                    float2 o = make_float2(acc[s][nb][0] + bx, acc[s][nb][1] + by);
                    *(float2*)(obase + (long long)rA * OUTC + cc) = o;
                }
                if (rB < NN) {
                    float2 o = make_float2(acc[s][nb][2] + bx, acc[s][nb][3] + by);
                    *(float2*)(obase + (long long)rB * OUTC + cc) = o;
                }
            }
        }
    }
}

// ---------------------------------------------------------------------------
extern "C" void kernel_launch(void* const* d_in, const int* in_sizes, int n_in,
                              void* d_out, int out_size) {
    const float* x  = (const float*)d_in[0];
    const void*  ei = d_in[1];
    const float* W1 = (const float*)d_in[2];
    const float* b1 = (const float*)d_in[3];
    const float* W2 = (const float*)d_in[4];
    const float* b2 = (const float*)d_in[5];
    float*       out = (float*)d_out;

    k_deg_init<<<(NN + 255) / 256, 256>>>((const unsigned*)ei);
    k_deg_count<<<(EE + 255) / 256, 256>>>(ei);
    k_dinv_self<<<(NN * 32 + 255) / 256, 256>>>(x);            // warp/node
    k_scatter<<<(int)(((long long)EE * 32 + 255) / 256), 256>>>(ei, x); // warp/edge
    k_split_a<<<(int)(((long long)NN * KP + 255) / 256), 256>>>();

    cudaFuncSetAttribute(k_gemm, cudaFuncAttributeMaxDynamicSharedMemorySize,
                         GEMM_SMEM);
    k_gemm<<<148, 256, GEMM_SMEM>>>(W1, b1, W2, b2, out);
}